// round 7
// baseline (speedup 1.0000x reference)
#include <cuda_runtime.h>

// SPU transformer bounds propagation — elementwise over (N,2) float32 pairs.
// spu(x) = x>=0 ? x*x - 0.5 : sigmoid(-x) - 1
// For x<0:  sigmoid(-x) - 1 = -0.5*tanh(x/2) - 0.5   (one MUFU.TANH)
//
// Selection (per row, l <= u):
//   neg  (u<=0):       lower=vl,   upper=vu
//   pos  (l>=0):       lower=0,    upper=0
//   cross, vu>=vl:     lower=-0.5, upper=vu    (sign(slope)==sign(vu-vl), u-l>0)
//   cross, vu< vl:     lower=0,    upper=vl
//
// Roofline status: kernel is at the B300 LTS streaming cap (~6300 B/cyc,
// path-independent). 128 MiB of L1<->L2 traffic / ~7.3 TB/s = ~18.3 us floor.
// This round targets the only remaining slack: wave structure. Single exact
// wave (148 SMs x 8 CTAs = 1184 blocks), grid-stride, unroll-2 for MLP,
// so the LTS stays saturated from ramp to drain with ±1-iteration imbalance
// instead of a 46%-populated trailing wave.

__device__ __forceinline__ float tanh_approx(float x) {
    float y;
    asm("tanh.approx.f32 %0, %1;" : "=f"(y) : "f"(x));
    return y;
}

__device__ __forceinline__ float spu(float x) {
    float q = fmaf(x, x, -0.5f);
    float t = tanh_approx(0.5f * x);
    float n = fmaf(-0.5f, t, -0.5f);
    return (x >= 0.0f) ? q : n;
}

__device__ __forceinline__ void spu_pair(float l, float u, float& lower, float& upper) {
    float vl = spu(l);
    float vu = spu(u);

    if (u <= 0.0f) {                 // neg
        lower = vl;  upper = vu;
    } else if (l >= 0.0f) {          // pos
        lower = 0.0f; upper = 0.0f;
    } else if (vu >= vl) {           // cross & slope >= 0
        lower = -0.5f; upper = vu;
    } else {                         // cross & slope < 0
        lower = 0.0f; upper = vl;
    }
}

__device__ __forceinline__ void ldg256(const float* p, float r[8]) {
    asm volatile("ld.global.nc.v8.f32 {%0,%1,%2,%3,%4,%5,%6,%7}, [%8];"
                 : "=f"(r[0]), "=f"(r[1]), "=f"(r[2]), "=f"(r[3]),
                   "=f"(r[4]), "=f"(r[5]), "=f"(r[6]), "=f"(r[7])
                 : "l"(p));
}

__device__ __forceinline__ void stg256(float* p, const float r[8]) {
    asm volatile("st.global.v8.f32 [%0], {%1,%2,%3,%4,%5,%6,%7,%8};"
                 :: "l"(p),
                    "f"(r[0]), "f"(r[1]), "f"(r[2]), "f"(r[3]),
                    "f"(r[4]), "f"(r[5]), "f"(r[6]), "f"(r[7])
                 : "memory");
}

__device__ __forceinline__ void spu_oct(const float a[8], float r[8]) {
    spu_pair(a[0], a[1], r[0], r[1]);
    spu_pair(a[2], a[3], r[2], r[3]);
    spu_pair(a[4], a[5], r[4], r[5]);
    spu_pair(a[6], a[7], r[6], r[7]);
}

__global__ void __launch_bounds__(256)
spu_bounds_kernel(const float* __restrict__ in, float* __restrict__ out, int n8) {
    int stride = gridDim.x * blockDim.x;           // 303,104
    int i = blockIdx.x * blockDim.x + threadIdx.x;

    // Steady state: two independent 256-bit loads in flight per thread.
    for (; i + stride < n8; i += 2 * stride) {
        int j = i + stride;
        float a0[8], a1[8];
        ldg256(in + (size_t)i * 8, a0);
        ldg256(in + (size_t)j * 8, a1);

        float r0[8], r1[8];
        spu_oct(a0, r0);
        spu_oct(a1, r1);

        stg256(out + (size_t)i * 8, r0);
        stg256(out + (size_t)j * 8, r1);
    }
    // Remainder (at most one group per thread).
    if (i < n8) {
        float a0[8], r0[8];
        ldg256(in + (size_t)i * 8, a0);
        spu_oct(a0, r0);
        stg256(out + (size_t)i * 8, r0);
    }
}

extern "C" void kernel_launch(void* const* d_in, const int* in_sizes, int n_in,
                              void* d_out, int out_size) {
    const float* in = (const float*)d_in[0];
    float* out = (float*)d_out;

    int total_floats = in_sizes[0];     // N*2 = 16,777,216
    int n8 = total_floats / 8;          // 2,097,152 32-byte groups

    // Single exact wave: 148 SMs x 8 resident CTAs of 256 threads.
    const int threads = 256;
    const int blocks = 148 * 8;         // 1184
    spu_bounds_kernel<<<blocks, threads>>>(in, out, n8);
}

// round 8
// speedup vs baseline: 1.0056x; 1.0056x over previous
#include <cuda_runtime.h>

// SPU transformer bounds propagation — elementwise over (N,2) float32 pairs.
// spu(x) = x>=0 ? x*x - 0.5 : sigmoid(-x) - 1
// For x<0:  sigmoid(-x) - 1 = -0.5*tanh(x/2) - 0.5   (one MUFU.TANH)
//
// Selection (per row, l <= u):
//   neg  (u<=0):  lower=vl,   upper=vu
//   pos  (l>=0):  lower=0,    upper=0
//   cross:        upper = max(vl,vu)          (cpos->vu is max; cneg->vl is max)
//                 lower = (vu>=vl) ? -0.5 : 0
//
// Memory path (the point of this round): loads via ld.global.cg — cache at
// L2 only, no L1 allocation. The stream has zero reuse; .nc loads were
// polluting L1 (41% busy) for nothing. If an L1tex wavefront serializer was
// the hidden 18us wall, this removes the read stream from it.
// Shape: R4's proven best — 4096 blocks x 256 threads, one-shot, MLP=2x256-bit.

__device__ __forceinline__ float tanh_approx(float x) {
    float y;
    asm("tanh.approx.f32 %0, %1;" : "=f"(y) : "f"(x));
    return y;
}

__device__ __forceinline__ float spu(float x) {
    float q = fmaf(x, x, -0.5f);
    float t = tanh_approx(0.5f * x);
    float n = fmaf(-0.5f, t, -0.5f);
    return (x >= 0.0f) ? q : n;
}

__device__ __forceinline__ void spu_pair(float l, float u, float& lower, float& upper) {
    float vl = spu(l);
    float vu = spu(u);

    if (u <= 0.0f) {                         // neg
        lower = vl;
        upper = vu;
    } else if (l >= 0.0f) {                  // pos
        lower = 0.0f;
        upper = 0.0f;
    } else {                                 // cross: u-l > 0 strictly
        lower = (vu >= vl) ? -0.5f : 0.0f;   // sign(slope) == sign(vu-vl)
        upper = fmaxf(vl, vu);               // cpos->vu, cneg->vl — both are the max
    }
}

__device__ __forceinline__ void ldg256_cg(const float* p, float r[8]) {
    asm volatile("ld.global.cg.v8.f32 {%0,%1,%2,%3,%4,%5,%6,%7}, [%8];"
                 : "=f"(r[0]), "=f"(r[1]), "=f"(r[2]), "=f"(r[3]),
                   "=f"(r[4]), "=f"(r[5]), "=f"(r[6]), "=f"(r[7])
                 : "l"(p));
}

__device__ __forceinline__ void stg256(float* p, const float r[8]) {
    asm volatile("st.global.v8.f32 [%0], {%1,%2,%3,%4,%5,%6,%7,%8};"
                 :: "l"(p),
                    "f"(r[0]), "f"(r[1]), "f"(r[2]), "f"(r[3]),
                    "f"(r[4]), "f"(r[5]), "f"(r[6]), "f"(r[7])
                 : "memory");
}

__device__ __forceinline__ void spu_oct(const float a[8], float r[8]) {
    spu_pair(a[0], a[1], r[0], r[1]);
    spu_pair(a[2], a[3], r[2], r[3]);
    spu_pair(a[4], a[5], r[4], r[5]);
    spu_pair(a[6], a[7], r[6], r[7]);
}

__global__ void __launch_bounds__(256)
spu_bounds_kernel(const float* __restrict__ in, float* __restrict__ out,
                  int n8, int stride8) {
    int t = blockIdx.x * blockDim.x + threadIdx.x;
    int i0 = t;
    int i1 = t + stride8;

    if (i1 < n8) {
        // Two independent 256-bit L2-only loads issued back-to-back.
        float a0[8], a1[8];
        ldg256_cg(in + (size_t)i0 * 8, a0);
        ldg256_cg(in + (size_t)i1 * 8, a1);

        float r0[8], r1[8];
        spu_oct(a0, r0);
        spu_oct(a1, r1);

        stg256(out + (size_t)i0 * 8, r0);
        stg256(out + (size_t)i1 * 8, r1);
    } else if (i0 < n8) {
        float a0[8], r0[8];
        ldg256_cg(in + (size_t)i0 * 8, a0);
        spu_oct(a0, r0);
        stg256(out + (size_t)i0 * 8, r0);
    }
}

extern "C" void kernel_launch(void* const* d_in, const int* in_sizes, int n_in,
                              void* d_out, int out_size) {
    const float* in = (const float*)d_in[0];
    float* out = (float*)d_out;

    int total_floats = in_sizes[0];     // N*2 = 16,777,216
    int n8 = total_floats / 8;          // 2,097,152 32-byte groups

    const int threads = 256;
    const int per_thread = 2;           // two 256-bit groups per thread
    int blocks = (n8 + threads * per_thread - 1) / (threads * per_thread);  // 4096
    int stride8 = blocks * threads;     // 1,048,576

    spu_bounds_kernel<<<blocks, threads>>>(in, out, n8, stride8);
}

// round 9
// speedup vs baseline: 1.0960x; 1.0899x over previous
#include <cuda_runtime.h>

// SPU transformer bounds propagation — elementwise over (N,2) float32 pairs.
// spu(x) = x>=0 ? x*x - 0.5 : sigmoid(-x) - 1
// For x<0:  sigmoid(-x) - 1 = -0.5*tanh(x/2) - 0.5   (one MUFU.TANH)
//
// Selection (per row, l <= u):
//   neg  (u<=0):  lower=vl,   upper=vu
//   pos  (l>=0):  lower=0,    upper=0
//   cross:        lower = (vu>=vl) ? -0.5 : 0     (sign(slope)==sign(vu-vl), u-l>0)
//                 upper = max(vl, vu)             (cpos->vu, cneg->vl — both the max)
//
// Roofline status (rounds 2-8 experiment matrix): kernel sits at the B300
// path-independent LTS streaming cap (~6300 B/cyc ~= 7.3 TB/s @NAT).
// 134 MB of L1<->L2 traffic / 7.3 TB/s = ~18.3 us — the measured floor across
// every MLP / vector width / cache policy / grid shape / occupancy variant.
// This is the locked-in best configuration:
//   - 256-bit .nc loads (lowest measured kernel time, R4)
//   - evict_first stores (best measured harness time, R5; write-once stream,
//     keeps input L2-resident across graph replays)
//   - 4096 blocks x 256 threads, one-shot, MLP = 2 x 256-bit per thread
//   - minimal selection tree (compare replaces slope division; max replaces
//     the cross-case nested select)

__device__ __forceinline__ float tanh_approx(float x) {
    float y;
    asm("tanh.approx.f32 %0, %1;" : "=f"(y) : "f"(x));
    return y;
}

__device__ __forceinline__ float spu(float x) {
    float q = fmaf(x, x, -0.5f);
    float t = tanh_approx(0.5f * x);
    float n = fmaf(-0.5f, t, -0.5f);
    return (x >= 0.0f) ? q : n;
}

__device__ __forceinline__ void spu_pair(float l, float u, float& lower, float& upper) {
    float vl = spu(l);
    float vu = spu(u);

    if (u <= 0.0f) {                         // neg: both endpoints <= 0
        lower = vl;
        upper = vu;
    } else if (l >= 0.0f) {                  // pos
        lower = 0.0f;
        upper = 0.0f;
    } else {                                 // cross: l < 0 < u, so u-l > 0 strictly
        lower = (vu >= vl) ? -0.5f : 0.0f;
        upper = fmaxf(vl, vu);
    }
}

__device__ __forceinline__ void ldg256(const float* p, float r[8]) {
    asm volatile("ld.global.nc.v8.f32 {%0,%1,%2,%3,%4,%5,%6,%7}, [%8];"
                 : "=f"(r[0]), "=f"(r[1]), "=f"(r[2]), "=f"(r[3]),
                   "=f"(r[4]), "=f"(r[5]), "=f"(r[6]), "=f"(r[7])
                 : "l"(p));
}

__device__ __forceinline__ void stg256_ef(float* p, const float r[8]) {
    asm volatile("st.global.L2::evict_first.v8.f32 [%0], {%1,%2,%3,%4,%5,%6,%7,%8};"
                 :: "l"(p),
                    "f"(r[0]), "f"(r[1]), "f"(r[2]), "f"(r[3]),
                    "f"(r[4]), "f"(r[5]), "f"(r[6]), "f"(r[7])
                 : "memory");
}

__device__ __forceinline__ void spu_oct(const float a[8], float r[8]) {
    spu_pair(a[0], a[1], r[0], r[1]);
    spu_pair(a[2], a[3], r[2], r[3]);
    spu_pair(a[4], a[5], r[4], r[5]);
    spu_pair(a[6], a[7], r[6], r[7]);
}

__global__ void __launch_bounds__(256)
spu_bounds_kernel(const float* __restrict__ in, float* __restrict__ out,
                  int n8, int stride8) {
    int t = blockIdx.x * blockDim.x + threadIdx.x;
    int i0 = t;
    int i1 = t + stride8;

    if (i1 < n8) {
        // Two independent 256-bit loads issued back-to-back (MLP=2).
        float a0[8], a1[8];
        ldg256(in + (size_t)i0 * 8, a0);
        ldg256(in + (size_t)i1 * 8, a1);

        float r0[8], r1[8];
        spu_oct(a0, r0);
        spu_oct(a1, r1);

        stg256_ef(out + (size_t)i0 * 8, r0);
        stg256_ef(out + (size_t)i1 * 8, r1);
    } else if (i0 < n8) {
        float a0[8], r0[8];
        ldg256(in + (size_t)i0 * 8, a0);
        spu_oct(a0, r0);
        stg256_ef(out + (size_t)i0 * 8, r0);
    }
}

extern "C" void kernel_launch(void* const* d_in, const int* in_sizes, int n_in,
                              void* d_out, int out_size) {
    const float* in = (const float*)d_in[0];
    float* out = (float*)d_out;

    int total_floats = in_sizes[0];     // N*2 = 16,777,216
    int n8 = total_floats / 8;          // 2,097,152 32-byte groups

    const int threads = 256;
    const int per_thread = 2;           // two 256-bit groups per thread
    int blocks = (n8 + threads * per_thread - 1) / (threads * per_thread);  // 4096
    int stride8 = blocks * threads;     // 1,048,576

    spu_bounds_kernel<<<blocks, threads>>>(in, out, n8, stride8);
}